// round 2
// baseline (speedup 1.0000x reference)
#include <cuda_runtime.h>

// out[N, D] = x[N, D] + params[D]
// N = 16384, D = 4096, fp32. Pure HBM-streaming broadcast add (512 MiB traffic).
//
// Layout: one block per row. 256 threads x 4 float4 each = 1024 float4 = 4096
// floats = one full row. Params float4 index = threadIdx.x + k*256, which is
// blockIdx-independent -> params (16 KB) stays L1/L2 hot across all blocks.
// 4 independent front-batched LDG.128 per thread maximizes MLP.

static constexpr int N_ROWS = 16384;
static constexpr int D_COLS = 4096;
static constexpr int D_VEC4 = D_COLS / 4;        // 1024 float4 per row
static constexpr int THREADS = 256;
static constexpr int V_PER_THREAD = D_VEC4 / THREADS;  // 4

__global__ void __launch_bounds__(THREADS, 8)
broadcast_add_kernel(const float4* __restrict__ x,
                     const float4* __restrict__ params,
                     float4* __restrict__ out) {
    const long long row_base = (long long)blockIdx.x * D_VEC4;
    const int t = threadIdx.x;

    // Front-batched independent loads (MLP = 4 streaming + 4 L2-hit).
    float4 xv[V_PER_THREAD];
    float4 pv[V_PER_THREAD];
#pragma unroll
    for (int k = 0; k < V_PER_THREAD; k++) {
        xv[k] = x[row_base + t + k * THREADS];
    }
#pragma unroll
    for (int k = 0; k < V_PER_THREAD; k++) {
        pv[k] = __ldg(&params[t + k * THREADS]);
    }

#pragma unroll
    for (int k = 0; k < V_PER_THREAD; k++) {
        float4 ov;
        ov.x = xv[k].x + pv[k].x;
        ov.y = xv[k].y + pv[k].y;
        ov.z = xv[k].z + pv[k].z;
        ov.w = xv[k].w + pv[k].w;
        out[row_base + t + k * THREADS] = ov;
    }
}

extern "C" void kernel_launch(void* const* d_in, const int* in_sizes, int n_in,
                              void* d_out, int out_size) {
    const float4* x      = (const float4*)d_in[0];
    const float4* params = (const float4*)d_in[1];
    float4* out          = (float4*)d_out;

    broadcast_add_kernel<<<N_ROWS, THREADS>>>(x, params, out);
}

// round 5
// speedup vs baseline: 1.0004x; 1.0004x over previous
#include <cuda_runtime.h>

// out[N, D] = x[N, D] + params[D]
// N = 16384, D = 4096, fp32. Pure HBM-streaming broadcast add (512 MiB traffic).
//
// R2 ncu: dram=81.5%, HBM=6461 GB/s, issue=6.8% -> HBM-bound, huge issue slack.
// This version: 2 rows per block (8 float4/thread, front-batched -> MLP=8),
// streaming cache hints (__ldcs/__stcs) to keep the 512 MiB stream from
// thrashing L2 and to ease DRAM read/write turnaround.
// Params: index t + k*256 (mod 1024) -> 4 unique vectors, reused for both rows.

static constexpr int N_ROWS = 16384;
static constexpr int D_COLS = 4096;
static constexpr int D_VEC4 = D_COLS / 4;          // 1024 float4 per row
static constexpr int THREADS = 256;
static constexpr int ROWS_PER_BLOCK = 2;
static constexpr int V_PER_ROW = D_VEC4 / THREADS; // 4
static constexpr int V_PER_THREAD = V_PER_ROW * ROWS_PER_BLOCK; // 8

__global__ void __launch_bounds__(THREADS)
broadcast_add_kernel(const float4* __restrict__ x,
                     const float4* __restrict__ params,
                     float4* __restrict__ out) {
    const long long base = (long long)blockIdx.x * (D_VEC4 * ROWS_PER_BLOCK);
    const int t = threadIdx.x;

    // 4 unique param vectors (L1/L2 hot, 16 KB total), default caching.
    float4 pv[V_PER_ROW];
#pragma unroll
    for (int k = 0; k < V_PER_ROW; k++) {
        pv[k] = __ldg(&params[t + k * THREADS]);
    }

    // 8 front-batched streaming loads (evict-first).
    float4 xv[V_PER_THREAD];
#pragma unroll
    for (int k = 0; k < V_PER_THREAD; k++) {
        xv[k] = __ldcs(&x[base + t + k * THREADS]);
    }

#pragma unroll
    for (int k = 0; k < V_PER_THREAD; k++) {
        float4 ov;
        const float4 p = pv[k & (V_PER_ROW - 1)];
        ov.x = xv[k].x + p.x;
        ov.y = xv[k].y + p.y;
        ov.z = xv[k].z + p.z;
        ov.w = xv[k].w + p.w;
        __stcs(&out[base + t + k * THREADS], ov);
    }
}

extern "C" void kernel_launch(void* const* d_in, const int* in_sizes, int n_in,
                              void* d_out, int out_size) {
    const float4* x      = (const float4*)d_in[0];
    const float4* params = (const float4*)d_in[1];
    float4* out          = (float4*)d_out;

    broadcast_add_kernel<<<N_ROWS / ROWS_PER_BLOCK, THREADS>>>(x, params, out);
}